// round 12
// baseline (speedup 1.0000x reference)
#include <cuda_runtime.h>
#include <cstdint>
#include <cstddef>

#define T_STEPS 4096
#define HD      512
#define NC      4880
#define G3      1536
#define SCAN_CTAS 32
#define WPC     16            // warps (hidden indices) per CTA

// ---------------- scratch (static device globals; no allocation) ----------------
__device__ float g_visit[(size_t)T_STEPS * HD];     // 8 MB
__device__ float g_gi[(size_t)T_STEPS * G3];        // 25 MB
__device__ float g_hs[(size_t)T_STEPS * HD];        // 8 MB (plain history for epilogue)
__device__ float g_hring[2][HD][32];                // 128 KB ring: (value, epoch)/line
__device__ float g_logits[T_STEPS];
__device__ float g_alpha[T_STEPS];

// ---------------- generic fp32 SIMT GEMM: C[M,N] = A x B (+bias) ----------------
template <bool A_KMAJ, bool B_KMAJ, bool BIAS>
__global__ __launch_bounds__(256)
void gemm_kernel(const float* __restrict__ A, const float* __restrict__ B,
                 const float* __restrict__ bias, float* __restrict__ C,
                 int M, int N, int K, int lda, int ldb, int ldc)
{
    constexpr int BM = 128, BN = 64, BK = 16;
    __shared__ float As[BK][BM + 4];
    __shared__ float Bs[BK][BN + 4];

    const int tid = threadIdx.x;
    const int tx  = tid & 15;
    const int ty  = tid >> 4;
    const int m0  = blockIdx.y * BM;
    const int n0  = blockIdx.x * BN;

    float acc[8][4];
#pragma unroll
    for (int i = 0; i < 8; i++)
#pragma unroll
        for (int j = 0; j < 4; j++) acc[i][j] = 0.f;

    for (int k0 = 0; k0 < K; k0 += BK) {
        if (A_KMAJ) {
#pragma unroll
            for (int it = 0; it < 2; it++) {
                int idx = tid + it * 256;
                int kk  = idx >> 5;
                int mm4 = idx & 31;
                float4 v = *(const float4*)&A[(size_t)(k0 + kk) * lda + m0 + mm4 * 4];
                *(float4*)&As[kk][mm4 * 4] = v;
            }
        } else {
#pragma unroll
            for (int it = 0; it < 2; it++) {
                int idx = tid + it * 256;
                int mm  = idx >> 2;
                int k4  = idx & 3;
                float4 v = *(const float4*)&A[(size_t)(m0 + mm) * lda + k0 + k4 * 4];
                As[k4 * 4 + 0][mm] = v.x;
                As[k4 * 4 + 1][mm] = v.y;
                As[k4 * 4 + 2][mm] = v.z;
                As[k4 * 4 + 3][mm] = v.w;
            }
        }
        if (B_KMAJ) {
            int kk  = tid >> 4;
            int nn4 = tid & 15;
            float4 v = *(const float4*)&B[(size_t)(k0 + kk) * ldb + n0 + nn4 * 4];
            *(float4*)&Bs[kk][nn4 * 4] = v;
        } else {
            int nn = tid >> 2;
            int k4 = tid & 3;
            float4 v = *(const float4*)&B[(size_t)(nn + n0) * ldb + k0 + k4 * 4];
            Bs[k4 * 4 + 0][nn] = v.x;
            Bs[k4 * 4 + 1][nn] = v.y;
            Bs[k4 * 4 + 2][nn] = v.z;
            Bs[k4 * 4 + 3][nn] = v.w;
        }
        __syncthreads();

#pragma unroll
        for (int kk = 0; kk < BK; kk++) {
            float4 a0 = *(const float4*)&As[kk][ty * 8];
            float4 a1 = *(const float4*)&As[kk][ty * 8 + 4];
            float4 b0 = *(const float4*)&Bs[kk][tx * 4];
            float a[8] = {a0.x, a0.y, a0.z, a0.w, a1.x, a1.y, a1.z, a1.w};
            float b[4] = {b0.x, b0.y, b0.z, b0.w};
#pragma unroll
            for (int i = 0; i < 8; i++)
#pragma unroll
                for (int j = 0; j < 4; j++) acc[i][j] += a[i] * b[j];
        }
        __syncthreads();
    }

    float4 bv = make_float4(0.f, 0.f, 0.f, 0.f);
    if (BIAS) bv = *(const float4*)&bias[n0 + tx * 4];
#pragma unroll
    for (int i = 0; i < 8; i++) {
        int m = m0 + ty * 8 + i;
        float4 v;
        v.x = acc[i][0] + bv.x;
        v.y = acc[i][1] + bv.y;
        v.z = acc[i][2] + bv.z;
        v.w = acc[i][3] + bv.w;
        *(float4*)&C[(size_t)m * ldc + n0 + tx * 4] = v;
    }
}

// ---------------- reset ring epochs (every replay) ----------------
__global__ __launch_bounds__(1024)
void ring_reset_kernel()
{
    int i = blockIdx.x * 1024 + threadIdx.x;   // grid covers 2*HD*32 floats
    ((float*)g_hring)[i] = 0.f;
}

// ---------------- volatile / delay helpers ----------------
__device__ __forceinline__ float2 ldv2(const float* p)
{
    float2 v;
    asm volatile("ld.volatile.global.v2.f32 {%0,%1}, [%2];"
                 : "=f"(v.x), "=f"(v.y) : "l"(p) : "memory");
    return v;
}
__device__ __forceinline__ void stv2(float* p, float a, float b)
{
    asm volatile("st.volatile.global.v2.f32 [%0], {%1,%2};"
                 :: "l"(p), "f"(a), "f"(b) : "memory");
}
// dependent-FMA delay chain: n * 4 cycles of in-order issue spacing
__device__ __forceinline__ void delay_chain(float& x, int n)
{
#pragma unroll
    for (int i = 0; i < 32; i++) {
        if (i >= n) break;
        asm volatile("fma.rn.f32 %0, %0, 0f3F800001, 0f00000000;" : "+f"(x));
    }
}
// batched spaced poll: 3 independent in-flight samples ~120cyc apart
__device__ __forceinline__ float poll_line(const float* line, unsigned want)
{
    float2 a = ldv2(line);                     // fast path
    if (__float_as_uint(a.y) == want) return a.x;
    float dummy = 1.0000001f;
    for (;;) {
        float2 s0 = ldv2(line);
        delay_chain(dummy, 30);
        float2 s1 = ldv2(line);
        delay_chain(dummy, 30);
        float2 s2 = ldv2(line);
        if (__float_as_uint(s0.y) == want) { a = s0; break; }
        if (__float_as_uint(s1.y) == want) { a = s1; break; }
        if (__float_as_uint(s2.y) == want) { a = s2; break; }
    }
    // consume dummy so the chains can't be dead-code eliminated
    return a.x + (dummy - dummy);
}
__device__ __forceinline__ float tanh_fast(float x)
{
    float e = __expf(2.f * x);
    return 1.f - 2.f / (e + 1.f);
}

// ---------------- GRU scan v10: 32 CTAs x 512 threads, 1 line per thread ------
// Warp w owns j = bid*16 + w (3 W_hh rows in regs, 48 floats/lane). Per step:
// thread tid polls ONE (value,epoch) 8B packet (its own cache line) with
// batched spaced sampling (3 in-flight probes ~120cyc apart -> poll-phase
// quantization ~150cyc instead of a full ~430cyc L2 RT), deposits to SMEM,
// one barrier, dots from SMEM against register weights, gates on lane0,
// publish (value,epoch=t+1) to the ring. Depth-2 epoch ring as validated in v5.
__global__ __launch_bounds__(512)
void gru_scan10_kernel(const float* __restrict__ W_hh, const float* __restrict__ b_hh,
                       const float* __restrict__ gi)
{
    __shared__ float h_s[2][HD];

    const int tid  = threadIdx.x;
    const int w    = tid >> 5;
    const int lane = tid & 31;
    const int j    = blockIdx.x * WPC + w;

    // --- weights into registers (once) ---
    float4 wr4[4], wz4[4], wn4[4];
    {
        const float4* pr = (const float4*)(W_hh + (size_t)j * HD)            + lane * 4;
        const float4* pz = (const float4*)(W_hh + (size_t)(HD + j) * HD)     + lane * 4;
        const float4* pn = (const float4*)(W_hh + (size_t)(2 * HD + j) * HD) + lane * 4;
#pragma unroll
        for (int q = 0; q < 4; q++) { wr4[q] = pr[q]; wz4[q] = pz[q]; wn4[q] = pn[q]; }
    }
    float bhr = 0.f, bhz = 0.f, bhn = 0.f;
    if (lane == 0) {
        bhr = __ldg(b_hh + j);
        bhz = __ldg(b_hh + HD + j);
        bhn = __ldg(b_hh + 2 * HD + j);
    }

    // zero initial-state buffer (t=0 reads buf 0)
    h_s[0][tid] = 0.f;

    // gi prefetch for t=0 (lane0)
    float gr = 0.f, gz = 0.f, gn = 0.f;
    if (lane == 0) {
        gr = __ldg(gi + j);
        gz = __ldg(gi + HD + j);
        gn = __ldg(gi + 2 * HD + j);
    }
    __syncthreads();

    float hj = 0.f;   // h_{t-1}[j]

    for (int t = 0; t < T_STEPS; t++) {
        const int buf = t & 1;

        // prefetch next step's gi (independent; flies during poll/compute)
        float grn = 0.f, gzn = 0.f, gnn = 0.f;
        if (lane == 0 && t + 1 < T_STEPS) {
            const float* gt = gi + (size_t)(t + 1) * G3;
            grn = __ldg(gt + j);
            gzn = __ldg(gt + HD + j);
            gnn = __ldg(gt + 2 * HD + j);
        }

        if (t > 0) {
            // poll this thread's single value of h_{t-1}; expect epoch == t
            const int s = (t - 1) & 1;
            float v = poll_line(&g_hring[s][tid][0], (unsigned)t);
            h_s[buf][tid] = v;
            __syncthreads();
        }

        // --- three 512-dots, 16 h elems per lane from SMEM, weights in regs ---
        float ar = 0.f, az = 0.f, an = 0.f;
#pragma unroll
        for (int q = 0; q < 4; q++) {
            float4 hv = *(const float4*)&h_s[buf][lane * 16 + q * 4];
            ar += hv.x * wr4[q].x + hv.y * wr4[q].y + hv.z * wr4[q].z + hv.w * wr4[q].w;
            az += hv.x * wz4[q].x + hv.y * wz4[q].y + hv.z * wz4[q].z + hv.w * wz4[q].w;
            an += hv.x * wn4[q].x + hv.y * wn4[q].y + hv.z * wn4[q].z + hv.w * wn4[q].w;
        }
        // packed butterfly: (ar,az) share one 64-bit shuffle chain
        double pk;
        {
            float2 t2 = make_float2(ar, az);
            pk = *reinterpret_cast<double*>(&t2);
        }
#pragma unroll
        for (int o = 16; o > 0; o >>= 1) {
            double po = __shfl_xor_sync(0xffffffffu, pk, o);
            float2 a2 = *reinterpret_cast<float2*>(&pk);
            float2 b2 = *reinterpret_cast<float2*>(&po);
            a2.x += b2.x; a2.y += b2.y;
            pk = *reinterpret_cast<double*>(&a2);
            an += __shfl_xor_sync(0xffffffffu, an, o);
        }
        {
            float2 a2 = *reinterpret_cast<float2*>(&pk);
            ar = a2.x; az = a2.y;
        }

        if (lane == 0) {
            if (t > 0) hj = h_s[buf][j];
            float r  = 1.f / (1.f + __expf(-(gr + ar + bhr)));
            float z  = 1.f / (1.f + __expf(-(gz + az + bhz)));
            float nv = tanh_fast(gn + r * (an + bhn));
            float hn = (1.f - z) * nv + z * hj;
            // publish (value, epoch=t+1) as one 8B packet in j's own line
            stv2(&g_hring[t & 1][j][0], hn, __uint_as_float((unsigned)(t + 1)));
            // plain history store for the epilogue (off critical path)
            g_hs[(size_t)t * HD + j] = hn;
            hj = hn;
        }

        gr = grn; gz = gzn; gn = gnn;
    }
}

// ---------------- logits[t] = dot(hs[t], w_att) ----------------
__global__ __launch_bounds__(256)
void logits_kernel(const float* __restrict__ w_att)
{
    __shared__ float watt[HD];
    const int tid  = threadIdx.x;
    const int w    = tid >> 5;
    const int lane = tid & 31;
    watt[tid]       = w_att[tid];
    watt[tid + 256] = w_att[tid + 256];
    __syncthreads();

    int t = blockIdx.x * 8 + w;
    const float* h = g_hs + (size_t)t * HD;
    float acc = 0.f;
    int base = lane * 16;
#pragma unroll
    for (int i = 0; i < 16; i += 4) {
        float4 hv = *(const float4*)&h[base + i];
        float4 wv = *(const float4*)&watt[base + i];
        acc += hv.x * wv.x + hv.y * wv.y + hv.z * wv.z + hv.w * wv.w;
    }
#pragma unroll
    for (int off = 16; off > 0; off >>= 1)
        acc += __shfl_down_sync(0xffffffffu, acc, off);
    if (lane == 0) g_logits[t] = acc;
}

// ---------------- softmax over 4096 logits; also zero d_out ----------------
__global__ __launch_bounds__(1024)
void softmax_kernel(float* __restrict__ out)
{
    __shared__ float red[32];
    const int tid  = threadIdx.x;
    const int lane = tid & 31;
    const int wrp  = tid >> 5;

    float m = -1e30f;
    for (int i = tid; i < T_STEPS; i += 1024) m = fmaxf(m, g_logits[i]);
#pragma unroll
    for (int o = 16; o > 0; o >>= 1) m = fmaxf(m, __shfl_xor_sync(0xffffffffu, m, o));
    if (lane == 0) red[wrp] = m;
    __syncthreads();
    if (wrp == 0) {
        float v = red[lane];
#pragma unroll
        for (int o = 16; o > 0; o >>= 1) v = fmaxf(v, __shfl_xor_sync(0xffffffffu, v, o));
        if (lane == 0) red[0] = v;
    }
    __syncthreads();
    m = red[0];
    __syncthreads();

    float s = 0.f;
    for (int i = tid; i < T_STEPS; i += 1024) {
        float e = __expf(g_logits[i] - m);
        g_alpha[i] = e;
        s += e;
    }
#pragma unroll
    for (int o = 16; o > 0; o >>= 1) s += __shfl_xor_sync(0xffffffffu, s, o);
    if (lane == 0) red[wrp] = s;
    __syncthreads();
    if (wrp == 0) {
        float v = red[lane];
#pragma unroll
        for (int o = 16; o > 0; o >>= 1) v += __shfl_xor_sync(0xffffffffu, v, o);
        if (lane == 0) red[0] = v;
    }
    __syncthreads();
    float inv = 1.f / red[0];
    for (int i = tid; i < T_STEPS; i += 1024) g_alpha[i] *= inv;

    if (tid < HD) out[tid] = 0.f;
}

// ---------------- out[d] += sum_t alpha[t] * hs[t][d] ----------------
__global__ __launch_bounds__(256)
void wsum_kernel(float* __restrict__ out)
{
    const int tid = threadIdx.x;
    const int d   = tid * 2;
    float ax = 0.f, ay = 0.f;
    int t0 = blockIdx.x * 64;
#pragma unroll 4
    for (int tt = 0; tt < 64; tt++) {
        int t = t0 + tt;
        float a = g_alpha[t];
        float2 hv = *(const float2*)&g_hs[(size_t)t * HD + d];
        ax += a * hv.x;
        ay += a * hv.y;
    }
    atomicAdd(out + d, ax);
    atomicAdd(out + d + 1, ay);
}

// ---------------- launcher ----------------
extern "C" void kernel_launch(void* const* d_in, const int* in_sizes, int n_in,
                              void* d_out, int out_size)
{
    const float* H     = (const float*)d_in[0];
    // d_in[1] = TE (unused)
    const float* X_emb = (const float*)d_in[2];
    const float* W_ih  = (const float*)d_in[3];
    const float* W_hh  = (const float*)d_in[4];
    const float* b_ih  = (const float*)d_in[5];
    const float* b_hh  = (const float*)d_in[6];
    const float* w_att = (const float*)d_in[7];
    float* out = (float*)d_out;

    float* visit; float* gi;
    cudaGetSymbolAddress((void**)&visit, g_visit);
    cudaGetSymbolAddress((void**)&gi, g_gi);

    // 0) reset the epoch ring (128 KB)
    ring_reset_kernel<<<(2 * HD * 32) / 1024, 1024>>>();
    // 1) visit_emb[4096,512] = H^T @ X_emb
    {
        dim3 grid(HD / 64, T_STEPS / 128);
        gemm_kernel<true, true, false><<<grid, 256>>>(
            H, X_emb, nullptr, visit, T_STEPS, HD, NC, T_STEPS, HD, HD);
    }
    // 2) gi[4096,1536] = visit_emb @ W_ih^T + b_ih
    {
        dim3 grid(G3 / 64, T_STEPS / 128);
        gemm_kernel<false, false, true><<<grid, 256>>>(
            visit, W_ih, b_ih, gi, T_STEPS, G3, HD, HD, HD, G3);
    }
    // 3) sequential GRU scan (single-line poll + batched spaced sampling)
    gru_scan10_kernel<<<SCAN_CTAS, 512>>>(W_hh, b_hh, gi);
    // 4) attention logits
    logits_kernel<<<T_STEPS / 8, 256>>>(w_att);
    // 5) softmax (+ zero out)
    softmax_kernel<<<1, 1024>>>(out);
    // 6) weighted sum
    wsum_kernel<<<T_STEPS / 64, 256>>>(out);
}

// round 13
// speedup vs baseline: 1.2305x; 1.2305x over previous
#include <cuda_runtime.h>
#include <cstdint>
#include <cstddef>

#define T_STEPS 4096
#define HD      512
#define NC      4880
#define G3      1536
#define SCAN_CTAS 32
#define NPKT    256           // 2 values per packet

// ---------------- scratch (static device globals; no allocation) ----------------
__device__ float g_visit[(size_t)T_STEPS * HD];     // 8 MB
__device__ float g_gi[(size_t)T_STEPS * G3];        // 25 MB
__device__ float g_hs[(size_t)T_STEPS * HD];        // 8 MB (plain history for epilogue)
__device__ float g_ring[2][NPKT][32];               // 64 KB: 1 line per 2-value packet
__device__ float g_logits[T_STEPS];
__device__ float g_alpha[T_STEPS];

// ---------------- generic fp32 SIMT GEMM: C[M,N] = A x B (+bias) ----------------
template <bool A_KMAJ, bool B_KMAJ, bool BIAS>
__global__ __launch_bounds__(256)
void gemm_kernel(const float* __restrict__ A, const float* __restrict__ B,
                 const float* __restrict__ bias, float* __restrict__ C,
                 int M, int N, int K, int lda, int ldb, int ldc)
{
    constexpr int BM = 128, BN = 64, BK = 16;
    __shared__ float As[BK][BM + 4];
    __shared__ float Bs[BK][BN + 4];

    const int tid = threadIdx.x;
    const int tx  = tid & 15;
    const int ty  = tid >> 4;
    const int m0  = blockIdx.y * BM;
    const int n0  = blockIdx.x * BN;

    float acc[8][4];
#pragma unroll
    for (int i = 0; i < 8; i++)
#pragma unroll
        for (int j = 0; j < 4; j++) acc[i][j] = 0.f;

    for (int k0 = 0; k0 < K; k0 += BK) {
        if (A_KMAJ) {
#pragma unroll
            for (int it = 0; it < 2; it++) {
                int idx = tid + it * 256;
                int kk  = idx >> 5;
                int mm4 = idx & 31;
                float4 v = *(const float4*)&A[(size_t)(k0 + kk) * lda + m0 + mm4 * 4];
                *(float4*)&As[kk][mm4 * 4] = v;
            }
        } else {
#pragma unroll
            for (int it = 0; it < 2; it++) {
                int idx = tid + it * 256;
                int mm  = idx >> 2;
                int k4  = idx & 3;
                float4 v = *(const float4*)&A[(size_t)(m0 + mm) * lda + k0 + k4 * 4];
                As[k4 * 4 + 0][mm] = v.x;
                As[k4 * 4 + 1][mm] = v.y;
                As[k4 * 4 + 2][mm] = v.z;
                As[k4 * 4 + 3][mm] = v.w;
            }
        }
        if (B_KMAJ) {
            int kk  = tid >> 4;
            int nn4 = tid & 15;
            float4 v = *(const float4*)&B[(size_t)(k0 + kk) * ldb + n0 + nn4 * 4];
            *(float4*)&Bs[kk][nn4 * 4] = v;
        } else {
            int nn = tid >> 2;
            int k4 = tid & 3;
            float4 v = *(const float4*)&B[(size_t)(nn + n0) * ldb + k0 + k4 * 4];
            Bs[k4 * 4 + 0][nn] = v.x;
            Bs[k4 * 4 + 1][nn] = v.y;
            Bs[k4 * 4 + 2][nn] = v.z;
            Bs[k4 * 4 + 3][nn] = v.w;
        }
        __syncthreads();

#pragma unroll
        for (int kk = 0; kk < BK; kk++) {
            float4 a0 = *(const float4*)&As[kk][ty * 8];
            float4 a1 = *(const float4*)&As[kk][ty * 8 + 4];
            float4 b0 = *(const float4*)&Bs[kk][tx * 4];
            float a[8] = {a0.x, a0.y, a0.z, a0.w, a1.x, a1.y, a1.z, a1.w};
            float b[4] = {b0.x, b0.y, b0.z, b0.w};
#pragma unroll
            for (int i = 0; i < 8; i++)
#pragma unroll
                for (int j = 0; j < 4; j++) acc[i][j] += a[i] * b[j];
        }
        __syncthreads();
    }

    float4 bv = make_float4(0.f, 0.f, 0.f, 0.f);
    if (BIAS) bv = *(const float4*)&bias[n0 + tx * 4];
#pragma unroll
    for (int i = 0; i < 8; i++) {
        int m = m0 + ty * 8 + i;
        float4 v;
        v.x = acc[i][0] + bv.x;
        v.y = acc[i][1] + bv.y;
        v.z = acc[i][2] + bv.z;
        v.w = acc[i][3] + bv.w;
        *(float4*)&C[(size_t)m * ldc + n0 + tx * 4] = v;
    }
}

// ---------------- reset ring epochs (every replay) ----------------
__global__ __launch_bounds__(1024)
void ring_reset_kernel()
{
    int i = blockIdx.x * 1024 + threadIdx.x;   // grid covers 2*NPKT*32 floats
    ((float*)g_ring)[i] = 0.f;
}

// ---------------- volatile / math helpers ----------------
__device__ __forceinline__ float4 ldv4(const float* p)
{
    float4 v;
    asm volatile("ld.volatile.global.v4.f32 {%0,%1,%2,%3}, [%4];"
                 : "=f"(v.x), "=f"(v.y), "=f"(v.z), "=f"(v.w) : "l"(p) : "memory");
    return v;
}
__device__ __forceinline__ void stv4(float* p, float a, float b, float c, float d)
{
    asm volatile("st.volatile.global.v4.f32 [%0], {%1,%2,%3,%4};"
                 :: "l"(p), "f"(a), "f"(b), "f"(c), "f"(d) : "memory");
}
__device__ __forceinline__ void fma2(unsigned long long& acc,
                                     unsigned long long a, unsigned long long b)
{
    asm("fma.rn.f32x2 %0, %1, %2, %0;" : "+l"(acc) : "l"(a), "l"(b));
}
__device__ __forceinline__ float2 unpk(unsigned long long v)
{
    return *reinterpret_cast<float2*>(&v);
}
__device__ __forceinline__ float tanh_fast(float x)
{
    float e = __expf(2.f * x);
    return 1.f - 2.f / (e + 1.f);
}

// ---------------- GRU scan v11: 32 CTAs x 256 thr, 2-value self-flag packets --
// Warp w of CTA c owns jA=16c+2w, jB=jA+1 (6 W_hh rows in regs as f32x2; 48
// FFMA2 per lane per step). Publish: lane0 emits ONE st.volatile.v4
// (hA, hB, epoch=t+1, 0) into packet (8c+w)'s own 128B line -> detect IS data
// arrival (1 L2 RT), 256 packets, 32 sync participants, no counters/fences.
// Consume: thread m polls packet m (one v4 load), deposits 2 floats to SMEM,
// one barrier. Depth-2 epoch ring (safety argument as validated in v5).
__global__ __launch_bounds__(256)
void gru_scan11_kernel(const float* __restrict__ W_hh, const float* __restrict__ b_hh,
                       const float* __restrict__ gi)
{
    __shared__ float h_s[2][HD];

    const int tid  = threadIdx.x;
    const int w    = tid >> 5;
    const int lane = tid & 31;
    const int c    = blockIdx.x;
    const int jA   = c * 16 + 2 * w;
    const int jB   = jA + 1;
    const int pkt  = c * 8 + w;          // this warp's packet index (2*pkt == jA)

    // --- weights into registers: 2 indices x 3 gates x 16 elems, f32x2 packed ---
    unsigned long long wAr[8], wAz[8], wAn[8], wBr[8], wBz[8], wBn[8];
    {
        const unsigned long long* pAr =
            (const unsigned long long*)(W_hh + (size_t)jA * HD + lane * 16);
        const unsigned long long* pAz =
            (const unsigned long long*)(W_hh + (size_t)(HD + jA) * HD + lane * 16);
        const unsigned long long* pAn =
            (const unsigned long long*)(W_hh + (size_t)(2 * HD + jA) * HD + lane * 16);
        const unsigned long long* pBr =
            (const unsigned long long*)(W_hh + (size_t)jB * HD + lane * 16);
        const unsigned long long* pBz =
            (const unsigned long long*)(W_hh + (size_t)(HD + jB) * HD + lane * 16);
        const unsigned long long* pBn =
            (const unsigned long long*)(W_hh + (size_t)(2 * HD + jB) * HD + lane * 16);
#pragma unroll
        for (int q = 0; q < 8; q++) {
            wAr[q] = pAr[q]; wAz[q] = pAz[q]; wAn[q] = pAn[q];
            wBr[q] = pBr[q]; wBz[q] = pBz[q]; wBn[q] = pBn[q];
        }
    }
    // biases on all lanes (broadcast loads)
    const float bArh = __ldg(b_hh + jA);
    const float bAzh = __ldg(b_hh + HD + jA);
    const float bAnh = __ldg(b_hh + 2 * HD + jA);
    const float bBrh = __ldg(b_hh + jB);
    const float bBzh = __ldg(b_hh + HD + jB);
    const float bBnh = __ldg(b_hh + 2 * HD + jB);

    // zero initial-state buffer (t=0 reads buf 0)
    h_s[0][tid]       = 0.f;
    h_s[0][tid + 256] = 0.f;

    // gi for t=0 on all lanes (broadcast)
    float gAr = __ldg(gi + jA), gAz = __ldg(gi + HD + jA), gAn = __ldg(gi + 2 * HD + jA);
    float gBr = __ldg(gi + jB), gBz = __ldg(gi + HD + jB), gBn = __ldg(gi + 2 * HD + jB);
    __syncthreads();

    for (int t = 0; t < T_STEPS; t++) {
        const int buf = t & 1;

        // prefetch next step's gi (broadcast; flies during poll/compute)
        float gArn = 0.f, gAzn = 0.f, gAnn = 0.f, gBrn = 0.f, gBzn = 0.f, gBnn = 0.f;
        if (t + 1 < T_STEPS) {
            const float* gt = gi + (size_t)(t + 1) * G3;
            gArn = __ldg(gt + jA); gAzn = __ldg(gt + HD + jA); gAnn = __ldg(gt + 2 * HD + jA);
            gBrn = __ldg(gt + jB); gBzn = __ldg(gt + HD + jB); gBnn = __ldg(gt + 2 * HD + jB);
        }

        if (t > 0) {
            // poll this thread's packet of h_{t-1}; epoch word == t means ready
            const float* lp = &g_ring[(t - 1) & 1][tid][0];
            float4 pk = ldv4(lp);
            while (__float_as_uint(pk.z) != (unsigned)t) pk = ldv4(lp);
            h_s[buf][2 * tid]     = pk.x;
            h_s[buf][2 * tid + 1] = pk.y;
            __syncthreads();
        }

        // --- six 512-dots (2 idx x 3 gates), 16 h elems per lane, f32x2 ---
        unsigned long long aAr = 0ull, aAz = 0ull, aAn = 0ull;
        unsigned long long aBr = 0ull, aBz = 0ull, aBn = 0ull;
        const unsigned long long* hp =
            (const unsigned long long*)&h_s[buf][lane * 16];
#pragma unroll
        for (int q = 0; q < 8; q++) {
            unsigned long long hv = hp[q];
            fma2(aAr, wAr[q], hv);
            fma2(aAz, wAz[q], hv);
            fma2(aAn, wAn[q], hv);
            fma2(aBr, wBr[q], hv);
            fma2(aBz, wBz[q], hv);
            fma2(aBn, wBn[q], hv);
        }
        float2 uAr = unpk(aAr), uAz = unpk(aAz), uAn = unpk(aAn);
        float2 uBr = unpk(aBr), uBz = unpk(aBz), uBn = unpk(aBn);
        float sAr = uAr.x + uAr.y, sAz = uAz.x + uAz.y, sAn = uAn.x + uAn.y;
        float sBr = uBr.x + uBr.y, sBz = uBz.x + uBz.y, sBn = uBn.x + uBn.y;

        // 5-level butterfly on 6 independent accumulators (all lanes get sums)
#pragma unroll
        for (int o = 16; o > 0; o >>= 1) {
            sAr += __shfl_xor_sync(0xffffffffu, sAr, o);
            sAz += __shfl_xor_sync(0xffffffffu, sAz, o);
            sAn += __shfl_xor_sync(0xffffffffu, sAn, o);
            sBr += __shfl_xor_sync(0xffffffffu, sBr, o);
            sBz += __shfl_xor_sync(0xffffffffu, sBz, o);
            sBn += __shfl_xor_sync(0xffffffffu, sBn, o);
        }

        // gates on all lanes (broadcast LDS for h_prev[jA], h_prev[jB])
        float hjA = h_s[buf][jA];
        float hjB = h_s[buf][jB];
        float rA  = 1.f / (1.f + __expf(-(gAr + sAr + bArh)));
        float zA  = 1.f / (1.f + __expf(-(gAz + sAz + bAzh)));
        float nA  = tanh_fast(gAn + rA * (sAn + bAnh));
        float hnA = (1.f - zA) * nA + zA * hjA;
        float rB  = 1.f / (1.f + __expf(-(gBr + sBr + bBrh)));
        float zB  = 1.f / (1.f + __expf(-(gBz + sBz + bBzh)));
        float nB  = tanh_fast(gBn + rB * (sBn + bBnh));
        float hnB = (1.f - zB) * nB + zB * hjB;

        if (lane == 0) {
            // single self-flagging packet: (hA, hB, epoch=t+1, 0)
            stv4(&g_ring[t & 1][pkt][0], hnA, hnB,
                 __uint_as_float((unsigned)(t + 1)), 0.f);
            // plain history store for the epilogue (off critical path)
            *(float2*)&g_hs[(size_t)t * HD + jA] = make_float2(hnA, hnB);
        }

        gAr = gArn; gAz = gAzn; gAn = gAnn;
        gBr = gBrn; gBz = gBzn; gBn = gBnn;
    }
}

// ---------------- logits[t] = dot(hs[t], w_att) ----------------
__global__ __launch_bounds__(256)
void logits_kernel(const float* __restrict__ w_att)
{
    __shared__ float watt[HD];
    const int tid  = threadIdx.x;
    const int w    = tid >> 5;
    const int lane = tid & 31;
    watt[tid]       = w_att[tid];
    watt[tid + 256] = w_att[tid + 256];
    __syncthreads();

    int t = blockIdx.x * 8 + w;
    const float* h = g_hs + (size_t)t * HD;
    float acc = 0.f;
    int base = lane * 16;
#pragma unroll
    for (int i = 0; i < 16; i += 4) {
        float4 hv = *(const float4*)&h[base + i];
        float4 wv = *(const float4*)&watt[base + i];
        acc += hv.x * wv.x + hv.y * wv.y + hv.z * wv.z + hv.w * wv.w;
    }
#pragma unroll
    for (int off = 16; off > 0; off >>= 1)
        acc += __shfl_down_sync(0xffffffffu, acc, off);
    if (lane == 0) g_logits[t] = acc;
}

// ---------------- softmax over 4096 logits; also zero d_out ----------------
__global__ __launch_bounds__(1024)
void softmax_kernel(float* __restrict__ out)
{
    __shared__ float red[32];
    const int tid  = threadIdx.x;
    const int lane = tid & 31;
    const int wrp  = tid >> 5;

    float m = -1e30f;
    for (int i = tid; i < T_STEPS; i += 1024) m = fmaxf(m, g_logits[i]);
#pragma unroll
    for (int o = 16; o > 0; o >>= 1) m = fmaxf(m, __shfl_xor_sync(0xffffffffu, m, o));
    if (lane == 0) red[wrp] = m;
    __syncthreads();
    if (wrp == 0) {
        float v = red[lane];
#pragma unroll
        for (int o = 16; o > 0; o >>= 1) v = fmaxf(v, __shfl_xor_sync(0xffffffffu, v, o));
        if (lane == 0) red[0] = v;
    }
    __syncthreads();
    m = red[0];
    __syncthreads();

    float s = 0.f;
    for (int i = tid; i < T_STEPS; i += 1024) {
        float e = __expf(g_logits[i] - m);
        g_alpha[i] = e;
        s += e;
    }
#pragma unroll
    for (int o = 16; o > 0; o >>= 1) s += __shfl_xor_sync(0xffffffffu, s, o);
    if (lane == 0) red[wrp] = s;
    __syncthreads();
    if (wrp == 0) {
        float v = red[lane];
#pragma unroll
        for (int o = 16; o > 0; o >>= 1) v += __shfl_xor_sync(0xffffffffu, v, o);
        if (lane == 0) red[0] = v;
    }
    __syncthreads();
    float inv = 1.f / red[0];
    for (int i = tid; i < T_STEPS; i += 1024) g_alpha[i] *= inv;

    if (tid < HD) out[tid] = 0.f;
}

// ---------------- out[d] += sum_t alpha[t] * hs[t][d] ----------------
__global__ __launch_bounds__(256)
void wsum_kernel(float* __restrict__ out)
{
    const int tid = threadIdx.x;
    const int d   = tid * 2;
    float ax = 0.f, ay = 0.f;
    int t0 = blockIdx.x * 64;
#pragma unroll 4
    for (int tt = 0; tt < 64; tt++) {
        int t = t0 + tt;
        float a = g_alpha[t];
        float2 hv = *(const float2*)&g_hs[(size_t)t * HD + d];
        ax += a * hv.x;
        ay += a * hv.y;
    }
    atomicAdd(out + d, ax);
    atomicAdd(out + d + 1, ay);
}

// ---------------- launcher ----------------
extern "C" void kernel_launch(void* const* d_in, const int* in_sizes, int n_in,
                              void* d_out, int out_size)
{
    const float* H     = (const float*)d_in[0];
    // d_in[1] = TE (unused)
    const float* X_emb = (const float*)d_in[2];
    const float* W_ih  = (const float*)d_in[3];
    const float* W_hh  = (const float*)d_in[4];
    const float* b_ih  = (const float*)d_in[5];
    const float* b_hh  = (const float*)d_in[6];
    const float* w_att = (const float*)d_in[7];
    float* out = (float*)d_out;

    float* visit; float* gi;
    cudaGetSymbolAddress((void**)&visit, g_visit);
    cudaGetSymbolAddress((void**)&gi, g_gi);

    // 0) reset the epoch ring (64 KB)
    ring_reset_kernel<<<(2 * NPKT * 32) / 1024, 1024>>>();
    // 1) visit_emb[4096,512] = H^T @ X_emb
    {
        dim3 grid(HD / 64, T_STEPS / 128);
        gemm_kernel<true, true, false><<<grid, 256>>>(
            H, X_emb, nullptr, visit, T_STEPS, HD, NC, T_STEPS, HD, HD);
    }
    // 2) gi[4096,1536] = visit_emb @ W_ih^T + b_ih
    {
        dim3 grid(G3 / 64, T_STEPS / 128);
        gemm_kernel<false, false, true><<<grid, 256>>>(
            visit, W_ih, b_ih, gi, T_STEPS, G3, HD, HD, HD, G3);
    }
    // 3) sequential GRU scan (2-value self-flagging packets, 32 CTAs)
    gru_scan11_kernel<<<SCAN_CTAS, 256>>>(W_hh, b_hh, gi);
    // 4) attention logits
    logits_kernel<<<T_STEPS / 8, 256>>>(w_att);
    // 5) softmax (+ zero out)
    softmax_kernel<<<1, 1024>>>(out);
    // 6) weighted sum
    wsum_kernel<<<T_STEPS / 64, 256>>>(out);
}